// round 10
// baseline (speedup 1.0000x reference)
#include <cuda_runtime.h>

#define IMG_SIZE 1280
#define NA 3
#define NC 80
#define BB 16
#define GG 160
#define CP 86              // 6 + NC
#define CC (NA * CP)       // 258
#define PLANE (GG * GG)    // 25600 floats per channel plane

#define NQUADS (BB * NA * PLANE / 4)   // 307200
#define THREADS 256

__device__ __forceinline__ float sigmoidf_(float v) {
    return 1.0f / (1.0f + expf(-v));
}

// One thread = 4 consecutive gx positions (float4 per channel plane).
// R7 structure (argmax phase first, boxes after) with a DEPTH-2 software
// pipeline: batches A (comparing), B and C (both in flight) -> ~8 outstanding
// LDG.128 per thread at steady state vs ~4 in R7, at the same 32 warps/SM.
__global__ __launch_bounds__(THREADS, 4) void anchor_decode_kernel(
    const float* __restrict__ x,
    const float* __restrict__ anchors,
    float* __restrict__ out)
{
    int tid = blockIdx.x * blockDim.x + threadIdx.x;
    if (tid >= NQUADS) return;

    const int quadsPerRow = GG / 4;           // 40
    int gx4  = (tid % quadsPerRow) * 4;
    int rest = tid / quadsPerRow;
    int gy   = rest % GG;
    int ba   = rest / GG;                     // b*NA + a
    int a    = ba % NA;
    int b    = ba / NA;

    const float* base = x + (size_t)(b * CC + a * CP) * PLANE + gy * GG + gx4;

    #define LD4(cp) (*reinterpret_cast<const float4*>(base + (size_t)(cp) * PLANE))

    // ---- Phase 1: argmax over 80 classes (channels 6..85) ----
    // first-max-wins: ascending class order + strict >.
    float bestv0 = -3.402823466e+38f, bestv1 = bestv0, bestv2 = bestv0, bestv3 = bestv0;
    float besti0 = 0.0f, besti1 = 0.0f, besti2 = 0.0f, besti3 = 0.0f;

    #define CMP(v, c) do {                                        \
        float fc_ = (float)(c);                                   \
        if ((v).x > bestv0) { bestv0 = (v).x; besti0 = fc_; }     \
        if ((v).y > bestv1) { bestv1 = (v).y; besti1 = fc_; }     \
        if ((v).z > bestv2) { bestv2 = (v).z; besti2 = fc_; }     \
        if ((v).w > bestv3) { bestv3 = (v).w; besti3 = fc_; }     \
    } while (0)

    // Depth-2 pipeline: A = oldest (compare now), B = mid-flight, C = newly issued.
    float4 A0 = LD4(6 + 0), A1 = LD4(6 + 1), A2 = LD4(6 + 2), A3 = LD4(6 + 3);
    float4 B0 = LD4(6 + 4), B1 = LD4(6 + 5), B2 = LD4(6 + 6), B3 = LD4(6 + 7);

    #pragma unroll 2
    for (int c = 0; c < NC - 8; c += 4) {
        float4 C0 = LD4(6 + c + 8);
        float4 C1 = LD4(6 + c + 9);
        float4 C2 = LD4(6 + c + 10);
        float4 C3 = LD4(6 + c + 11);
        CMP(A0, c + 0);
        CMP(A1, c + 1);
        CMP(A2, c + 2);
        CMP(A3, c + 3);
        A0 = B0; A1 = B1; A2 = B2; A3 = B3;
        B0 = C0; B1 = C1; B2 = C2; B3 = C3;
    }
    // Tail: A holds classes 72..75, B holds 76..79.
    CMP(A0, NC - 8); CMP(A1, NC - 7); CMP(A2, NC - 6); CMP(A3, NC - 5);
    CMP(B0, NC - 4); CMP(B1, NC - 3); CMP(B2, NC - 2); CMP(B3, NC - 1);
    #undef CMP

    // ---- Phase 2: box channels (0..5), compute, store ----
    float4 vx   = LD4(0);
    float4 vy   = LD4(1);
    float4 vw   = LD4(2);
    float4 vh   = LD4(3);
    float4 vyaw = LD4(4);
    float4 vconf= LD4(5);
    #undef LD4

    const float stride = (float)IMG_SIZE / (float)GG;  // 8.0
    float aw = __ldg(&anchors[a * 2 + 0]);
    float ah = __ldg(&anchors[a * 2 + 1]);

    float ox[4]  = {vx.x, vx.y, vx.z, vx.w};
    float oy[4]  = {vy.x, vy.y, vy.z, vy.w};
    float ow[4]  = {vw.x, vw.y, vw.z, vw.w};
    float oh[4]  = {vh.x, vh.y, vh.z, vh.w};
    float oyw[4] = {vyaw.x, vyaw.y, vyaw.z, vyaw.w};
    float ocf[4] = {vconf.x, vconf.y, vconf.z, vconf.w};
    float bi[4]  = {besti0, besti1, besti2, besti3};

    float o[28];
    #pragma unroll
    for (int j = 0; j < 4; j++) {
        float sx = sigmoidf_(ox[j]);
        float sy = sigmoidf_(oy[j]);
        o[j * 7 + 0] = floorf((sx + (float)(gx4 + j)) * stride);
        o[j * 7 + 1] = floorf((sy + (float)gy) * stride);
        o[j * 7 + 2] = expf(ow[j]) * aw;
        o[j * 7 + 3] = expf(oh[j]) * ah;
        o[j * 7 + 4] = oyw[j];
        o[j * 7 + 5] = sigmoidf_(ocf[j]);
        o[j * 7 + 6] = bi[j];
    }

    // out offset = pos*7 floats, pos%4==0 -> 112B-aligned: 7 float4 stores.
    float* op = out + ((size_t)ba * PLANE + (size_t)gy * GG + gx4) * 7;
    float4* op4 = reinterpret_cast<float4*>(op);
    #pragma unroll
    for (int k = 0; k < 7; k++) {
        op4[k] = make_float4(o[k * 4 + 0], o[k * 4 + 1],
                             o[k * 4 + 2], o[k * 4 + 3]);
    }
}

extern "C" void kernel_launch(void* const* d_in, const int* in_sizes, int n_in,
                              void* d_out, int out_size) {
    const float* x       = (const float*)d_in[0];
    // d_in[1] = target (unused by reference output)
    const float* anchors = (const float*)d_in[2];
    float* out = (float*)d_out;

    const int blocks = (NQUADS + THREADS - 1) / THREADS;  // 1200
    anchor_decode_kernel<<<blocks, THREADS>>>(x, anchors, out);
}

// round 11
// speedup vs baseline: 1.1635x; 1.1635x over previous
#include <cuda_runtime.h>

#define IMG_SIZE 1280
#define NA 3
#define NC 80
#define BB 16
#define GG 160
#define CP 86              // 6 + NC
#define CC (NA * CP)       // 258
#define PLANE (GG * GG)    // 25600 floats per channel plane

#define NQUADS (BB * NA * PLANE / 4)   // 307200
#define THREADS 256

__device__ __forceinline__ float sigmoidf_(float v) {
    return 1.0f / (1.0f + expf(-v));
}

// One thread = 4 consecutive gx positions (float4 per channel plane).
// R7 structure: phase-ordered, depth-1/batch-4 software-pipelined argmax
// (deepest pipeline that fits the 64-reg / 4-blocks-per-SM pin without
// spilling — R10 proved depth-2 spills). Box-channel loads hoisted before
// the tail compares so their latency overlaps the last compare work.
__global__ __launch_bounds__(THREADS, 4) void anchor_decode_kernel(
    const float* __restrict__ x,
    const float* __restrict__ anchors,
    float* __restrict__ out)
{
    int tid = blockIdx.x * blockDim.x + threadIdx.x;
    if (tid >= NQUADS) return;

    const int quadsPerRow = GG / 4;           // 40
    int gx4  = (tid % quadsPerRow) * 4;
    int rest = tid / quadsPerRow;
    int gy   = rest % GG;
    int ba   = rest / GG;                     // b*NA + a
    int a    = ba % NA;
    int b    = ba / NA;

    const float* base = x + (size_t)(b * CC + a * CP) * PLANE + gy * GG + gx4;

    #define LD4(cp) (*reinterpret_cast<const float4*>(base + (size_t)(cp) * PLANE))

    // ---- Phase 1: argmax over 80 classes (channels 6..85) ----
    // first-max-wins: ascending class order + strict >.
    float bestv0 = -3.402823466e+38f, bestv1 = bestv0, bestv2 = bestv0, bestv3 = bestv0;
    float besti0 = 0.0f, besti1 = 0.0f, besti2 = 0.0f, besti3 = 0.0f;

    #define CMP(v, c) do {                                        \
        float fc_ = (float)(c);                                   \
        if ((v).x > bestv0) { bestv0 = (v).x; besti0 = fc_; }     \
        if ((v).y > bestv1) { bestv1 = (v).y; besti1 = fc_; }     \
        if ((v).z > bestv2) { bestv2 = (v).z; besti2 = fc_; }     \
        if ((v).w > bestv3) { bestv3 = (v).w; besti3 = fc_; }     \
    } while (0)

    // Depth-1 software pipeline: load batch k+1 while comparing batch k.
    float4 cur0 = LD4(6 + 0);
    float4 cur1 = LD4(6 + 1);
    float4 cur2 = LD4(6 + 2);
    float4 cur3 = LD4(6 + 3);

    #pragma unroll 2
    for (int c = 0; c < NC - 4; c += 4) {
        float4 n0 = LD4(6 + c + 4);
        float4 n1 = LD4(6 + c + 5);
        float4 n2 = LD4(6 + c + 6);
        float4 n3 = LD4(6 + c + 7);
        CMP(cur0, c + 0);
        CMP(cur1, c + 1);
        CMP(cur2, c + 2);
        CMP(cur3, c + 3);
        cur0 = n0; cur1 = n1; cur2 = n2; cur3 = n3;
    }

    // Hoist phase-2 box loads so they fly during the tail compares.
    // Live here: cur(16) + box(24) + best(8) + addressing -> fits under 64.
    float4 vx   = LD4(0);
    float4 vy   = LD4(1);
    float4 vw   = LD4(2);
    float4 vh   = LD4(3);
    float4 vyaw = LD4(4);
    float4 vconf= LD4(5);

    CMP(cur0, NC - 4);
    CMP(cur1, NC - 3);
    CMP(cur2, NC - 2);
    CMP(cur3, NC - 1);
    #undef CMP
    #undef LD4

    // ---- Phase 2: compute + store ----
    const float stride = (float)IMG_SIZE / (float)GG;  // 8.0
    float aw = __ldg(&anchors[a * 2 + 0]);
    float ah = __ldg(&anchors[a * 2 + 1]);

    float ox[4]  = {vx.x, vx.y, vx.z, vx.w};
    float oy[4]  = {vy.x, vy.y, vy.z, vy.w};
    float ow[4]  = {vw.x, vw.y, vw.z, vw.w};
    float oh[4]  = {vh.x, vh.y, vh.z, vh.w};
    float oyw[4] = {vyaw.x, vyaw.y, vyaw.z, vyaw.w};
    float ocf[4] = {vconf.x, vconf.y, vconf.z, vconf.w};
    float bi[4]  = {besti0, besti1, besti2, besti3};

    float o[28];
    #pragma unroll
    for (int j = 0; j < 4; j++) {
        float sx = sigmoidf_(ox[j]);
        float sy = sigmoidf_(oy[j]);
        o[j * 7 + 0] = floorf((sx + (float)(gx4 + j)) * stride);
        o[j * 7 + 1] = floorf((sy + (float)gy) * stride);
        o[j * 7 + 2] = expf(ow[j]) * aw;
        o[j * 7 + 3] = expf(oh[j]) * ah;
        o[j * 7 + 4] = oyw[j];
        o[j * 7 + 5] = sigmoidf_(ocf[j]);
        o[j * 7 + 6] = bi[j];
    }

    // out offset = pos*7 floats, pos%4==0 -> 112B-aligned: 7 float4 stores.
    float* op = out + ((size_t)ba * PLANE + (size_t)gy * GG + gx4) * 7;
    float4* op4 = reinterpret_cast<float4*>(op);
    #pragma unroll
    for (int k = 0; k < 7; k++) {
        op4[k] = make_float4(o[k * 4 + 0], o[k * 4 + 1],
                             o[k * 4 + 2], o[k * 4 + 3]);
    }
}

extern "C" void kernel_launch(void* const* d_in, const int* in_sizes, int n_in,
                              void* d_out, int out_size) {
    const float* x       = (const float*)d_in[0];
    // d_in[1] = target (unused by reference output)
    const float* anchors = (const float*)d_in[2];
    float* out = (float*)d_out;

    const int blocks = (NQUADS + THREADS - 1) / THREADS;  // 1200
    anchor_decode_kernel<<<blocks, THREADS>>>(x, anchors, out);
}